// round 6
// baseline (speedup 1.0000x reference)
#include <cuda_runtime.h>

#define NT   128    // B*T
#define BB   16
#define TT   8
#define CC   512
#define C8   64
#define HW4  196    // 784/4
#define SLICES 16384           // NT*CC/4 rows-per-slice
#define TICKETS (SLICES + 1024)

// Scratch (no device allocation -> __device__ globals)
__device__ float g_xv[NT * CC];
__device__ float g_left[NT * C8];
__device__ float g_right[NT * C8];
__device__ float g_state[NT * C8];
__device__ int   g_ticket;
__device__ int   g_cnt_nt[NT];
__device__ int   g_cnt_b[BB];
__device__ int   g_flag[BB];

// Reset pipeline state every launch (graph replays reuse device globals).
__global__ void init_k() {
    int i = threadIdx.x;
    if (i == 0) g_ticket = 0;
    if (i < NT) g_cnt_nt[i] = 0;
    if (i < BB) { g_cnt_b[i] = 0; g_flag[i] = 0; }
}

// ---------------------------------------------------------------------------
// One fused pipelined kernel.
//  ticket k < 16384 : pool slice k (4 rows of batch k>>10, nt = k>>7)
//    - last finisher of an nt (128 slices) computes gemm+BN for that nt
//    - last nt-finisher of a batch (8 nts) runs the scan, sets flag[b]
//  ticket k >= 1024 : scale slice k-1024 of batch (k-1024)>>10 after flag.
//  x[b] is still L2-resident when scale(b) re-reads it.
// ---------------------------------------------------------------------------
__global__ void __launch_bounds__(256) mega_k(
    const float* __restrict__ x,
    const float* __restrict__ w1,
    const float* __restrict__ bn1g, const float* __restrict__ bn1b,
    const float* __restrict__ bn1m, const float* __restrict__ bn1v,
    const float* __restrict__ w2,
    const float* __restrict__ bn2g, const float* __restrict__ bn2b,
    const float* __restrict__ bn2m, const float* __restrict__ bn2v,
    const float* __restrict__ Wa_w, const float* __restrict__ Wa_b,
    const float* __restrict__ gamma_w, const float* __restrict__ gamma_b,
    float* __restrict__ out)
{
    __shared__ float  s_part[4][2];
    __shared__ float4 s_xv4[CC / 4];
    __shared__ int    s_tk, s_nt, s_b;

    int tid = threadIdx.x;
    if (tid == 0) s_tk = atomicAdd(&g_ticket, 1);
    __syncthreads();
    int tk = s_tk;

    // ======================= POOL phase =======================
    if (tk < SLICES) {
        int sub = tid >> 6, i = tid & 63;
        int row = tk * 4 + sub;
        const float4* xi = reinterpret_cast<const float4*>(x) + (size_t)row * HW4;
        float4 v0 = __ldg(xi + i);
        float4 v1 = __ldg(xi + i + 64);
        float4 v2 = __ldg(xi + i + 128);
        float s = 0.f;
        if (i < 4) { float4 tv = __ldg(xi + 192 + i); s = (tv.x + tv.y) + (tv.z + tv.w); }
        s += (v0.x + v0.y) + (v0.z + v0.w);
        s += (v1.x + v1.y) + (v1.z + v1.w);
        s += (v2.x + v2.y) + (v2.z + v2.w);
        #pragma unroll
        for (int o = 16; o; o >>= 1) s += __shfl_xor_sync(0xffffffffu, s, o);
        if ((i & 31) == 0) s_part[sub][i >> 5] = s;
        __syncthreads();
        if (i == 0) g_xv[row] = (s_part[sub][0] + s_part[sub][1]) * (1.0f / 784.0f);
        __threadfence();
        __syncthreads();

        int nt = tk >> 7;
        if (tid == 0) {
            int old = atomicAdd(&g_cnt_nt[nt], 1);
            s_nt = (old == 127) ? nt : -1;
        }
        __syncthreads();

        if (s_nt >= 0) {
            // -------- per-nt gemm + BN + ReLU (128 outputs, 512-dot each) --------
            __threadfence();                              // acquire g_xv
            if (tid < CC / 4)
                s_xv4[tid] = __ldg(reinterpret_cast<const float4*>(g_xv) + nt * (CC / 4) + tid);
            __syncthreads();
            if (tid < 128) {
                int half = tid >> 6, ch = tid & 63;
                const float* wsel = half ? w2   : w1;
                const float* gsel = half ? bn2g : bn1g;
                const float* bsel = half ? bn2b : bn1b;
                const float* msel = half ? bn2m : bn1m;
                const float* vsel = half ? bn2v : bn1v;
                const float4* wr = reinterpret_cast<const float4*>(wsel) + ch * (CC / 4);
                float a0 = 0.f, a1 = 0.f, a2 = 0.f, a3 = 0.f;
                #pragma unroll 8
                for (int k = 0; k < CC / 4; k++) {
                    float4 wv = __ldg(wr + k);
                    float4 xv = s_xv4[k];
                    a0 += xv.x * wv.x;
                    a1 += xv.y * wv.y;
                    a2 += xv.z * wv.z;
                    a3 += xv.w * wv.w;
                }
                float acc = (a0 + a1) + (a2 + a3);
                float sc  = __ldg(gsel + ch) * rsqrtf(__ldg(vsel + ch) + 1e-5f);
                float val = fmaxf((acc - __ldg(msel + ch)) * sc + __ldg(bsel + ch), 0.f);
                if (half == 0) g_left [nt * C8 + ch] = val;
                else           g_right[nt * C8 + ch] = val;
            }
            __threadfence();
            __syncthreads();

            int b = nt >> 3;
            if (tid == 0) {
                int old = atomicAdd(&g_cnt_b[b], 1);
                s_b = (old == TT - 1) ? b : -1;
            }
            __syncthreads();

            // -------- per-batch scan (warp 0 only, 8 sequential steps) --------
            if (s_b >= 0 && tid < 32) {
                __threadfence();                          // acquire g_left/g_right
                int bb   = s_b;
                int lane = tid;
                float L0[7], L1[7], R0[7], R1[7];
                #pragma unroll
                for (int t = 0; t < 7; t++) {
                    L0[t] = g_left [(bb * TT + t)     * C8 + lane];
                    L1[t] = g_left [(bb * TT + t)     * C8 + lane + 32];
                    R0[t] = g_right[(bb * TT + t + 1) * C8 + lane];
                    R1[t] = g_right[(bb * TT + t + 1) * C8 + lane + 32];
                }
                float gm0 = __ldg(gamma_w + lane);
                float gm1 = __ldg(gamma_w + lane + 32);
                float gm2 = __ldg(gamma_w + lane + 64);
                float gm3 = __ldg(gamma_w + lane + 96);
                float gb  = __ldg(gamma_b);
                float s0 = 1.f, s1 = 1.f;
                #pragma unroll
                for (int t = 0; t < TT; t++) {
                    float d0 = (t < TT - 1) ? (L0[t] - R0[t]) : 1.f;
                    float d1 = (t < TT - 1) ? (L1[t] - R1[t]) : 1.f;
                    float acc = d0 * gm0 + d1 * gm1 + s0 * gm2 + s1 * gm3;
                    #pragma unroll
                    for (int o = 16; o; o >>= 1) acc += __shfl_xor_sync(0xffffffffu, acc, o);
                    float g = 1.0f / (1.0f + __expf(-(acc + gb)));
                    s0 = d0 * g + s0 * (1.0f - g);
                    s1 = d1 * g + s1 * (1.0f - g);
                    g_state[(bb * TT + t) * C8 + lane]      = s0;
                    g_state[(bb * TT + t) * C8 + lane + 32] = s1;
                }
                __threadfence();
                __syncwarp();
                if (lane == 0) atomicExch(&g_flag[bb], 1);
            }
        }
    }

    // ======================= SCALE phase =======================
    if (tk >= 1024) {
        int q  = tk - 1024;
        int b  = q >> 10;
        if (tid == 0) {
            while (atomicAdd(&g_flag[b], 0) == 0) __nanosleep(128);
        }
        __syncthreads();
        __threadfence();                                  // acquire g_state

        int sub = tid >> 6, i = tid & 63;
        int row = q * 4 + sub;
        int nt  = row >> 9;
        int c   = row & (CC - 1);

        const float4* xi = reinterpret_cast<const float4*>(x)   + (size_t)row * HW4;
        float4*       xo = reinterpret_cast<float4*>(out)       + (size_t)row * HW4;

        float4 v0 = __ldg(xi + i);
        float4 v1 = __ldg(xi + i + 64);
        float4 v2 = __ldg(xi + i + 128);
        float4 v3;
        bool tail = (i < 4);
        if (tail) v3 = __ldg(xi + i + 192);

        float p = g_state[nt * C8 + i] * __ldg(Wa_w + c * C8 + i);
        #pragma unroll
        for (int o = 16; o; o >>= 1) p += __shfl_xor_sync(0xffffffffu, p, o);
        if ((i & 31) == 0) s_part[sub][i >> 5] = p;
        __syncthreads();
        float a = s_part[sub][0] + s_part[sub][1] + __ldg(Wa_b + c);
        float s = 1.0f / (1.0f + __expf(-a));

        v0.x *= s; v0.y *= s; v0.z *= s; v0.w *= s;
        v1.x *= s; v1.y *= s; v1.z *= s; v1.w *= s;
        v2.x *= s; v2.y *= s; v2.z *= s; v2.w *= s;
        __stcs(xo + i,       v0);
        __stcs(xo + i + 64,  v1);
        __stcs(xo + i + 128, v2);
        if (tail) {
            v3.x *= s; v3.y *= s; v3.z *= s; v3.w *= s;
            __stcs(xo + i + 192, v3);
        }
    }
}

// ---------------------------------------------------------------------------
extern "C" void kernel_launch(void* const* d_in, const int* in_sizes, int n_in,
                              void* d_out, int out_size) {
    const float* x       = (const float*)d_in[0];
    const float* w1      = (const float*)d_in[1];
    const float* bn1_g   = (const float*)d_in[2];
    const float* bn1_b   = (const float*)d_in[3];
    const float* bn1_m   = (const float*)d_in[4];
    const float* bn1_v   = (const float*)d_in[5];
    const float* w2      = (const float*)d_in[6];
    const float* bn2_g   = (const float*)d_in[7];
    const float* bn2_b   = (const float*)d_in[8];
    const float* bn2_m   = (const float*)d_in[9];
    const float* bn2_v   = (const float*)d_in[10];
    const float* Wa_w    = (const float*)d_in[11];
    const float* Wa_b    = (const float*)d_in[12];
    const float* gamma_w = (const float*)d_in[13];
    const float* gamma_b = (const float*)d_in[14];
    float* out = (float*)d_out;

    init_k<<<1, 256>>>();
    mega_k<<<TICKETS, 256>>>(x,
                             w1, bn1_g, bn1_b, bn1_m, bn1_v,
                             w2, bn2_g, bn2_b, bn2_m, bn2_v,
                             Wa_w, Wa_b, gamma_w, gamma_b, out);
}

// round 8
// speedup vs baseline: 3.3053x; 3.3053x over previous
#include <cuda_runtime.h>

#define NT   128    // B*T
#define BB   16
#define TT   8
#define CC   512
#define C8   64
#define HW4  196    // 784/4

// Scratch (no device allocation -> __device__ globals)
__device__ float g_xv[NT * CC];
__device__ float g_left[NT * C8];
__device__ float g_right[NT * C8];
__device__ float g_state[NT * C8];

// ---------------------------------------------------------------------------
// Kernel 1: spatial mean pool. 4 rows/block, 64 threads/row, float4 I/O.
// Ascending block order: at completion, L2 holds the TAIL of x.
// ---------------------------------------------------------------------------
__global__ void pool_k(const float* __restrict__ x) {
    __shared__ float s_part[4][2];
    int tid = threadIdx.x;
    int sub = tid >> 6, i = tid & 63;
    int row = blockIdx.x * 4 + sub;
    const float4* xi = reinterpret_cast<const float4*>(x) + (size_t)row * HW4;

    float4 v0 = xi[i];
    float4 v1 = xi[i + 64];
    float4 v2 = xi[i + 128];
    float s = 0.f;
    if (i < 4) { float4 tv = xi[i + 192]; s = (tv.x + tv.y) + (tv.z + tv.w); }
    s += (v0.x + v0.y) + (v0.z + v0.w);
    s += (v1.x + v1.y) + (v1.z + v1.w);
    s += (v2.x + v2.y) + (v2.z + v2.w);

    #pragma unroll
    for (int o = 16; o; o >>= 1) s += __shfl_xor_sync(0xffffffffu, s, o);
    if ((i & 31) == 0) s_part[sub][i >> 5] = s;
    __syncthreads();
    if (i == 0)
        g_xv[row] = (s_part[sub][0] + s_part[sub][1]) * (1.0f / 784.0f);
}

// ---------------------------------------------------------------------------
// Kernel 2: left = relu(BN(xv @ w1^T)), right = relu(BN(xv @ w2^T)).
// ---------------------------------------------------------------------------
__global__ void gemm_bn_k(const float* __restrict__ w1,
                          const float* __restrict__ bn1g, const float* __restrict__ bn1b,
                          const float* __restrict__ bn1m, const float* __restrict__ bn1v,
                          const float* __restrict__ w2,
                          const float* __restrict__ bn2g, const float* __restrict__ bn2b,
                          const float* __restrict__ bn2m, const float* __restrict__ bn2v) {
    __shared__ float sx[CC];
    int nt  = blockIdx.x;
    int tid = threadIdx.x;
    #pragma unroll
    for (int i = tid; i < CC; i += 128) sx[i] = g_xv[nt * CC + i];
    __syncthreads();

    int ch = tid & 63;
    const float* wsel = (tid < 64) ? w1   : w2;
    const float* gsel = (tid < 64) ? bn1g : bn2g;
    const float* bsel = (tid < 64) ? bn1b : bn2b;
    const float* msel = (tid < 64) ? bn1m : bn2m;
    const float* vsel = (tid < 64) ? bn1v : bn2v;

    const float4* wr4 = reinterpret_cast<const float4*>(wsel + ch * CC);
    const float4* sx4 = reinterpret_cast<const float4*>(sx);
    float a0 = 0.f, a1 = 0.f, a2 = 0.f, a3 = 0.f;
    #pragma unroll 8
    for (int k = 0; k < CC / 4; k++) {
        float4 wv = __ldg(wr4 + k);
        float4 xv = sx4[k];
        a0 += xv.x * wv.x;
        a1 += xv.y * wv.y;
        a2 += xv.z * wv.z;
        a3 += xv.w * wv.w;
    }
    float acc   = (a0 + a1) + (a2 + a3);
    float scale = gsel[ch] * rsqrtf(vsel[ch] + 1e-5f);
    float val   = fmaxf((acc - msel[ch]) * scale + bsel[ch], 0.f);
    if (tid < 64) g_left[nt * C8 + ch]  = val;
    else          g_right[nt * C8 + ch] = val;
}

// ---------------------------------------------------------------------------
// Kernel 3: register-resident gated scan. One block, 16 warps (warp = batch).
// ---------------------------------------------------------------------------
__global__ void scan_rec_k(const float* __restrict__ gamma_w,
                           const float* __restrict__ gamma_b) {
    int b    = threadIdx.x >> 5;          // 16 warps = 16 batches
    int lane = threadIdx.x & 31;

    float L0[7], L1[7], R0[7], R1[7];
    #pragma unroll
    for (int t = 0; t < 7; t++) {
        L0[t] = g_left [(b * TT + t)     * C8 + lane];
        L1[t] = g_left [(b * TT + t)     * C8 + lane + 32];
        R0[t] = g_right[(b * TT + t + 1) * C8 + lane];
        R1[t] = g_right[(b * TT + t + 1) * C8 + lane + 32];
    }
    float gm0 = __ldg(gamma_w + lane);
    float gm1 = __ldg(gamma_w + lane + 32);
    float gm2 = __ldg(gamma_w + lane + 64);
    float gm3 = __ldg(gamma_w + lane + 96);
    float gb  = __ldg(gamma_b);

    float s0 = 1.f, s1 = 1.f;             // initial state = padded ones
    #pragma unroll
    for (int t = 0; t < TT; t++) {
        float d0 = (t < TT - 1) ? (L0[t] - R0[t]) : 1.f;
        float d1 = (t < TT - 1) ? (L1[t] - R1[t]) : 1.f;
        float acc = d0 * gm0 + d1 * gm1 + s0 * gm2 + s1 * gm3;
        #pragma unroll
        for (int o = 16; o; o >>= 1) acc += __shfl_xor_sync(0xffffffffu, acc, o);
        float g = 1.0f / (1.0f + __expf(-(acc + gb)));
        s0 = d0 * g + s0 * (1.0f - g);
        s1 = d1 * g + s1 * (1.0f - g);
        g_state[(b * TT + t) * C8 + lane]      = s0;
        g_state[(b * TT + t) * C8 + lane + 32] = s1;
    }
}

// ---------------------------------------------------------------------------
// Kernel 4: fused attention + scale. REVERSED block order: first blocks read
// the tail of x, which pool just left resident in L2. Streaming stores keep
// the out stream from evicting x lines.
// ---------------------------------------------------------------------------
__global__ void scale_att_k(const float* __restrict__ x,
                            const float* __restrict__ Wa_w,
                            const float* __restrict__ Wa_b,
                            float* __restrict__ out) {
    __shared__ float s_part[4][2];
    int tid  = threadIdx.x;
    int sub  = tid >> 6, i = tid & 63;
    int rb   = gridDim.x - 1 - blockIdx.x;   // reversed
    int row  = rb * 4 + sub;                 // (nt*CC + c) row id
    int nt   = row >> 9;
    int c    = row & (CC - 1);

    const float4* xi = reinterpret_cast<const float4*>(x)   + (size_t)row * HW4;
    float4*       xo = reinterpret_cast<float4*>(out)       + (size_t)row * HW4;

    // issue bulk loads first (long-latency, overlap with sig computation)
    float4 v0 = __ldg(xi + i);
    float4 v1 = __ldg(xi + i + 64);
    float4 v2 = __ldg(xi + i + 128);
    float4 v3;
    bool tail = (i < 4);
    if (tail) v3 = __ldg(xi + i + 192);

    // inline attention dot: state[nt][i] * Wa[c][i], 64 threads, 1 elem each
    float p = g_state[nt * C8 + i] * __ldg(Wa_w + c * C8 + i);
    #pragma unroll
    for (int o = 16; o; o >>= 1) p += __shfl_xor_sync(0xffffffffu, p, o);
    if ((i & 31) == 0) s_part[sub][i >> 5] = p;
    __syncthreads();
    float a = s_part[sub][0] + s_part[sub][1] + __ldg(Wa_b + c);
    float s = 1.0f / (1.0f + __expf(-a));

    v0.x *= s; v0.y *= s; v0.z *= s; v0.w *= s;
    v1.x *= s; v1.y *= s; v1.z *= s; v1.w *= s;
    v2.x *= s; v2.y *= s; v2.z *= s; v2.w *= s;
    __stcs(xo + i,       v0);
    __stcs(xo + i + 64,  v1);
    __stcs(xo + i + 128, v2);
    if (tail) {
        v3.x *= s; v3.y *= s; v3.z *= s; v3.w *= s;
        __stcs(xo + i + 192, v3);
    }
}

// ---------------------------------------------------------------------------
extern "C" void kernel_launch(void* const* d_in, const int* in_sizes, int n_in,
                              void* d_out, int out_size) {
    const float* x       = (const float*)d_in[0];
    const float* w1      = (const float*)d_in[1];
    const float* bn1_g   = (const float*)d_in[2];
    const float* bn1_b   = (const float*)d_in[3];
    const float* bn1_m   = (const float*)d_in[4];
    const float* bn1_v   = (const float*)d_in[5];
    const float* w2      = (const float*)d_in[6];
    const float* bn2_g   = (const float*)d_in[7];
    const float* bn2_b   = (const float*)d_in[8];
    const float* bn2_m   = (const float*)d_in[9];
    const float* bn2_v   = (const float*)d_in[10];
    const float* Wa_w    = (const float*)d_in[11];
    const float* Wa_b    = (const float*)d_in[12];
    const float* gamma_w = (const float*)d_in[13];
    const float* gamma_b = (const float*)d_in[14];
    float* out = (float*)d_out;

    pool_k<<<(NT * CC) / 4, 256>>>(x);                       // 16384 blocks
    gemm_bn_k<<<NT, 128>>>(w1, bn1_g, bn1_b, bn1_m, bn1_v,
                           w2, bn2_g, bn2_b, bn2_m, bn2_v);
    scan_rec_k<<<1, 512>>>(gamma_w, gamma_b);                // 1 block, registers
    scale_att_k<<<(NT * CC) / 4, 256>>>(x, Wa_w, Wa_b, out); // 16384 blocks
}